// round 9
// baseline (speedup 1.0000x reference)
#include <cuda_runtime.h>
#include <stdint.h>

#define NN 100000
#define EE 3200000
#define TT 8
#define FF 64
#define NK (NN * TT)            // 800000 sort buckets (dst*8 + t)
#define SCAN_BLKS (NK / 256)    // 3125

// ---------------- device scratch (allocation-free) ----------------
__device__ float g_h1[(size_t)NN * FF];   // 25.6 MB
__device__ int   g_sedge[EE];             // src, sorted by (dst*8+t)
__device__ int   g_key[EE];               // cached sort key
__device__ int   g_psrc[EE];              // cached src
__device__ int   g_kcnt[NK];
__device__ int   g_off[NK + 1];
__device__ int   g_kcur[NK];
__device__ int   g_bsum[SCAN_BLKS + 3];
__device__ int   g_mode;                  // 1 = int64 indices, 0 = int32

#define FMA2(acc, a, b) asm("fma.rn.f32x2 %0, %1, %2, %0;" : "+l"(acc) : "l"(a), "l"(b))
__device__ __forceinline__ unsigned long long dup2(float v) {
    unsigned long long r;
    unsigned int b = __float_as_uint(v);
    asm("mov.b64 %0, {%1, %1};" : "=l"(r) : "r"(b));
    return r;
}
__device__ __forceinline__ unsigned long long pack2(float lo, float hi) {
    unsigned long long r;
    asm("mov.b64 %0, {%1, %2};" : "=l"(r) : "r"(__float_as_uint(lo)), "r"(__float_as_uint(hi)));
    return r;
}
__device__ __forceinline__ float2 unpack2(unsigned long long v) {
    unsigned int lo, hi;
    asm("mov.b64 {%0, %1}, %2;" : "=r"(lo), "=r"(hi) : "l"(v));
    return make_float2(__uint_as_float(lo), __uint_as_float(hi));
}

// ---------------- dtype detection ----------------
__global__ void k_detect(const int* __restrict__ ei) {
    __shared__ int any_nonzero;
    if (threadIdx.x == 0) any_nonzero = 0;
    __syncthreads();
    int v = ei[2 * threadIdx.x + 1];
    if (v != 0) atomicExch(&any_nonzero, 1);
    __syncthreads();
    if (threadIdx.x == 0) g_mode = (any_nonzero == 0) ? 1 : 0;
}

__global__ void k_zero_k(void) {
    int i = blockIdx.x * 256 + threadIdx.x;
    if (i < NK) g_kcnt[i] = 0;
}

// ---------------- histogram over key = dst*8 + t (caches key & src) --------
__global__ void k_hist(const void* __restrict__ ei_raw, const void* __restrict__ ti_raw) {
    int e = blockIdx.x * 256 + threadIdx.x;
    if (e >= EE) return;
    int src, dst, t;
    if (g_mode) {
        const long long* ei = (const long long*)ei_raw;
        const long long* ti = (const long long*)ti_raw;
        src = (int)ei[e];
        dst = (int)ei[(size_t)EE + e];
        t   = (int)ti[e];
    } else {
        const int* ei = (const int*)ei_raw;
        const int* ti = (const int*)ti_raw;
        src = ei[e];
        dst = ei[EE + e];
        t   = ti[e];
    }
    int key = dst * TT + t;
    g_key[e] = key;
    g_psrc[e] = src;
    atomicAdd(&g_kcnt[key], 1);
}

// ---------------- hierarchical scan ----------------
__global__ void __launch_bounds__(256) k_scan1(void) {
    __shared__ int sh[256];
    int i = blockIdx.x * 256 + threadIdx.x;
    int v = g_kcnt[i];
    sh[threadIdx.x] = v;
    __syncthreads();
#pragma unroll
    for (int off = 1; off < 256; off <<= 1) {
        int u = 0;
        if (threadIdx.x >= off) u = sh[threadIdx.x - off];
        __syncthreads();
        if (threadIdx.x >= off) sh[threadIdx.x] += u;
        __syncthreads();
    }
    g_off[i] = sh[threadIdx.x] - v;
    if (threadIdx.x == 255) g_bsum[blockIdx.x] = sh[255];
}

__global__ void __launch_bounds__(1024) k_scan2(void) {
    __shared__ int ps[1024];
    int tid = threadIdx.x;
    int base = tid * 4;
    int vals[4];
    int s = 0;
#pragma unroll
    for (int k = 0; k < 4; k++) {
        int idx = base + k;
        vals[k] = (idx < SCAN_BLKS) ? g_bsum[idx] : 0;
        s += vals[k];
    }
    ps[tid] = s;
    __syncthreads();
    for (int off = 1; off < 1024; off <<= 1) {
        int u = 0;
        if (tid >= off) u = ps[tid - off];
        __syncthreads();
        if (tid >= off) ps[tid] += u;
        __syncthreads();
    }
    int run = ps[tid] - s;
#pragma unroll
    for (int k = 0; k < 4; k++) {
        int idx = base + k;
        if (idx < SCAN_BLKS) g_bsum[idx] = run;
        run += vals[k];
    }
}

__global__ void __launch_bounds__(256) k_scan3(void) {
    int i = blockIdx.x * 256 + threadIdx.x;
    int v = g_off[i] + g_bsum[blockIdx.x];
    g_off[i] = v;
    g_kcur[i] = v;
    if (i == 0) g_off[NK] = EE;
}

// ---------------- permute: g_sedge sorted by (dst*8+t) ----------------
__global__ void k_permute(void) {
    int e = blockIdx.x * 256 + threadIdx.x;
    if (e >= EE) return;
    int key = __ldg(&g_key[e]);
    int pos = atomicAdd(&g_kcur[key], 1);
    g_sedge[pos] = __ldg(&g_psrc[e]);
}

// ---------------- fused: CSR aggregate (8-way ILP) + GEMM + bias + relu ----
// 256 thr = 8 warps; half-warp per dst (16 dsts/block).
// Phase A: all 8 t-buckets of a dst walked in LOCK-STEP -> MLP ~8.
// Phase B: [16,512] @ [512,64] with f32x2 FMAs, fused bias+relu.
__global__ void __launch_bounds__(256) k_fused(const float* __restrict__ in,
                                               const float* __restrict__ W,
                                               const float* __restrict__ bias,
                                               float* __restrict__ out) {
    __shared__ float xs[16][520];
    int tid = threadIdx.x;
    int warpid = tid >> 5, lane = tid & 31;
    int nb = blockIdx.x * 16;

    // ---- Phase A: bucket-parallel aggregate ----
    {
        int eh = lane >> 4;                // half-warp id
        int li = lane & 15;                // float4 column 0..15
        int slot = warpid * 2 + eh;        // 0..15
        int base = (nb + slot) * TT;
        const float4* x4 = (const float4*)in;

        int cur[TT], en[TT];
        int prev = __ldg(&g_off[base]);
#pragma unroll
        for (int t = 0; t < TT; t++) {
            cur[t] = prev;
            prev = __ldg(&g_off[base + t + 1]);
            en[t] = prev;
        }
        float4 acc[TT];
#pragma unroll
        for (int t = 0; t < TT; t++) acc[t] = make_float4(0.f, 0.f, 0.f, 0.f);

        bool any = true;
        while (any) {
            any = false;
#pragma unroll
            for (int t = 0; t < TT; t++) {
                if (cur[t] < en[t]) {
                    int src = __ldg(&g_sedge[cur[t]]);
                    float4 v = __ldg(&x4[(size_t)src * 16 + li]);
                    acc[t].x += v.x; acc[t].y += v.y;
                    acc[t].z += v.z; acc[t].w += v.w;
                    cur[t]++;
                    any = true;
                }
            }
        }
#pragma unroll
        for (int t = 0; t < TT; t++)
            *(float4*)&xs[slot][t * 64 + li * 4] = acc[t];
    }
    __syncthreads();

    // ---- Phase B ----
    int row = tid >> 4;                    // 0..15
    int fo4 = tid & 15;                    // float4 output column
    const float4* W4 = (const float4*)W;   // [512][16]

    unsigned long long a0 = 0, a1 = 0;
#pragma unroll 4
    for (int f4 = 0; f4 < 128; f4++) {
        float4 xv = *(const float4*)&xs[row][f4 * 4];
        float4 w0 = __ldg(&W4[(f4 * 4 + 0) * 16 + fo4]);
        float4 w1 = __ldg(&W4[(f4 * 4 + 1) * 16 + fo4]);
        float4 w2 = __ldg(&W4[(f4 * 4 + 2) * 16 + fo4]);
        float4 w3 = __ldg(&W4[(f4 * 4 + 3) * 16 + fo4]);
        unsigned long long x0 = dup2(xv.x), x1 = dup2(xv.y);
        unsigned long long x2 = dup2(xv.z), x3 = dup2(xv.w);
        FMA2(a0, x0, pack2(w0.x, w0.y)); FMA2(a1, x0, pack2(w0.z, w0.w));
        FMA2(a0, x1, pack2(w1.x, w1.y)); FMA2(a1, x1, pack2(w1.z, w1.w));
        FMA2(a0, x2, pack2(w2.x, w2.y)); FMA2(a1, x2, pack2(w2.z, w2.w));
        FMA2(a0, x3, pack2(w3.x, w3.y)); FMA2(a1, x3, pack2(w3.z, w3.w));
    }

    float4 bv = __ldg(&((const float4*)bias)[fo4]);
    float2 lo = unpack2(a0), hi = unpack2(a1);
    float4 r;
    r.x = fmaxf(lo.x + bv.x, 0.f);
    r.y = fmaxf(lo.y + bv.y, 0.f);
    r.z = fmaxf(hi.x + bv.z, 0.f);
    r.w = fmaxf(hi.y + bv.w, 0.f);
    ((float4*)out)[(size_t)(nb + row) * 16 + fo4] = r;
}

// ---------------- ssl = h2 @ Wssl + bssl ----------------
__global__ void __launch_bounds__(256) k_ssl(const float* __restrict__ h2,
                                             const float* __restrict__ Wssl,
                                             const float* __restrict__ bssl,
                                             float* __restrict__ out) {
    __shared__ float ws[64 * 64];
    __shared__ float hs[4 * 64];
    int tid = threadIdx.x;
    int nb  = blockIdx.x * 4;

    {
        float4* wsv = (float4*)ws;
        const float4* Wv = (const float4*)Wssl;
#pragma unroll
        for (int k = 0; k < 4; k++) wsv[tid + k * 256] = Wv[tid + k * 256];
        hs[tid] = h2[(size_t)nb * 64 + tid];
    }
    __syncthreads();

    int nl = tid >> 6;
    int fo = tid & 63;
    float a = __ldg(&bssl[fo]);
#pragma unroll 8
    for (int fin = 0; fin < 64; ++fin)
        a += hs[nl * 64 + fin] * ws[fin * 64 + fo];
    out[(size_t)(nb + nl) * 64 + fo] = a;
}

// ---------------- launch ----------------
extern "C" void kernel_launch(void* const* d_in, const int* in_sizes, int n_in,
                              void* d_out, int out_size) {
    const float* x    = (const float*)d_in[0];
    const void*  ei   = d_in[1];
    const void*  ti   = d_in[2];
    const float* W1   = (const float*)d_in[3];
    const float* b1   = (const float*)d_in[4];
    const float* W2   = (const float*)d_in[5];
    const float* b2   = (const float*)d_in[6];
    const float* Wssl = (const float*)d_in[7];
    const float* bssl = (const float*)d_in[8];
    float* out_h   = (float*)d_out;
    float* out_ssl = (float*)d_out + (size_t)NN * 64;

    float* dh1;  cudaGetSymbolAddress((void**)&dh1, g_h1);

    // counting sort by (dst*8 + t), hierarchical scan
    k_detect<<<1, 256>>>((const int*)ei);
    k_zero_k<<<SCAN_BLKS, 256>>>();
    k_hist<<<EE / 256, 256>>>(ei, ti);
    k_scan1<<<SCAN_BLKS, 256>>>();
    k_scan2<<<1, 1024>>>();
    k_scan3<<<SCAN_BLKS, 256>>>();
    k_permute<<<EE / 256, 256>>>();

    // fused layers (no atomics, no intermediate y)
    k_fused<<<NN / 16, 256>>>(x, W1, b1, dh1);
    k_fused<<<NN / 16, 256>>>(dh1, W2, b2, out_h);

    // ssl head
    k_ssl<<<NN / 4, 256>>>(out_h, Wssl, bssl, out_ssl);
}

// round 10
// speedup vs baseline: 1.5331x; 1.5331x over previous
#include <cuda_runtime.h>
#include <stdint.h>

#define NN 100000
#define EE 3200000
#define TT 8
#define FF 64
#define INIT_BLKS 391           // ceil(NN/256)

// ---------------- device scratch (allocation-free) ----------------
__device__ float g_y[(size_t)TT * NN * FF];   // 204.8 MB: y[t*N+n][f]
__device__ float g_h1[(size_t)NN * FF];       // 25.6 MB
__device__ float g_V1[64 * 512];              // permuted W1: V[fin][t*64+fout]
__device__ float g_V2[64 * 512];
__device__ int   g_pack[EE];                  // t*NN + src (payload)
__device__ int   g_edst[EE];                  // dst (sort key)
__device__ int   g_sedge[EE];                 // payload sorted by dst
__device__ int   g_cnt[NN];
__device__ int   g_off[NN];
__device__ int   g_kcur[NN];
__device__ int   g_total;
__device__ int   g_mode;                      // 1 = int64 indices, 0 = int32

#define FMA2(acc, a, b) asm("fma.rn.f32x2 %0, %1, %2, %0;" : "+l"(acc) : "l"(a), "l"(b))

// ---------------- init: mode detect + zero counters + permute W1/W2 --------
__global__ void __launch_bounds__(256) k_init(const int* __restrict__ ei,
                                              const float* __restrict__ W1,
                                              const float* __restrict__ W2) {
    int i = blockIdx.x * 256 + threadIdx.x;
    if (i < NN) g_cnt[i] = 0;
    if (i == 0) g_total = 0;

    // W permute: V[fin*512 + t*64+fo] = W[(t*64+fin)*64+fo]
    if (i < 32768) {
        int fin = i >> 9;
        int j   = i & 511;
        int t   = j >> 6;
        int fo  = j & 63;
        g_V1[i] = W1[((t << 6) + fin) * 64 + fo];
        g_V2[i] = W2[((t << 6) + fin) * 64 + fo];
    }

    // dtype detect (block 0): if int64, odd int32 words are all 0
    if (blockIdx.x == 0) {
        int v = ei[2 * threadIdx.x + 1];
        unsigned int ball = __ballot_sync(0xffffffffu, v != 0);
        __shared__ int nz[8];
        if ((threadIdx.x & 31) == 0) nz[threadIdx.x >> 5] = (ball != 0);
        __syncthreads();
        if (threadIdx.x == 0) {
            int any = 0;
            for (int w = 0; w < 8; w++) any |= nz[w];
            g_mode = any ? 0 : 1;
        }
    }
}

// ---------------- y[t*N+n][:] = in[n][:] @ W_t  (f32x2 packed FMA) ----------
__global__ void __launch_bounds__(128) k_gemm(const float* __restrict__ in,
                                              const float* __restrict__ V,
                                              float* __restrict__ y) {
    __shared__ float xs[16][64];
    int tid = threadIdx.x;
    int nb  = blockIdx.x * 16;

    {
        const float4* inv = (const float4*)(in + (size_t)nb * 64);
        float4* xsv = (float4*)&xs[0][0];
        xsv[tid]       = inv[tid];
        xsv[tid + 128] = inv[tid + 128];
    }
    __syncthreads();

    int jt = tid & 31;
    int ng = tid >> 5;

    unsigned long long acc[4][4][2];
#pragma unroll
    for (int i = 0; i < 4; i++)
#pragma unroll
        for (int s = 0; s < 4; s++) { acc[i][s][0] = 0ull; acc[i][s][1] = 0ull; }

    const ulonglong2* Vr = (const ulonglong2*)V;

#pragma unroll 4
    for (int fin = 0; fin < 64; ++fin) {
        unsigned long long xv[4];
#pragma unroll
        for (int i = 0; i < 4; i++) {
            unsigned int xb = __float_as_uint(xs[(ng << 2) + i][fin]);
            asm("mov.b64 %0, {%1, %1};" : "=l"(xv[i]) : "r"(xb));
        }
#pragma unroll
        for (int s = 0; s < 4; s++) {
            ulonglong2 w = __ldg(&Vr[fin * 128 + jt + s * 32]);
#pragma unroll
            for (int i = 0; i < 4; i++) {
                FMA2(acc[i][s][0], xv[i], w.x);
                FMA2(acc[i][s][1], xv[i], w.y);
            }
        }
    }

    ulonglong2* yv = (ulonglong2*)y;
#pragma unroll
    for (int s = 0; s < 4; s++) {
        int j4 = jt + s * 32;
        int t  = j4 >> 4;
        int c4 = j4 & 15;
#pragma unroll
        for (int i = 0; i < 4; i++) {
            int node = nb + (ng << 2) + i;
            ulonglong2 o;
            o.x = acc[i][s][0];
            o.y = acc[i][s][1];
            yv[(size_t)(t * NN + node) * 16 + c4] = o;
        }
    }
}

// ---------------- histogram over dst (caches key & payload) ----------------
__global__ void k_hist(const void* __restrict__ ei_raw, const void* __restrict__ ti_raw) {
    int e = blockIdx.x * 256 + threadIdx.x;
    if (e >= EE) return;
    int src, dst, t;
    if (g_mode) {
        const long long* ei = (const long long*)ei_raw;
        const long long* ti = (const long long*)ti_raw;
        src = (int)ei[e];
        dst = (int)ei[(size_t)EE + e];
        t   = (int)ti[e];
    } else {
        const int* ei = (const int*)ei_raw;
        const int* ti = (const int*)ti_raw;
        src = ei[e];
        dst = ei[EE + e];
        t   = ti[e];
    }
    g_pack[e] = t * NN + src;
    g_edst[e] = dst;
    atomicAdd(&g_cnt[dst], 1);
}

// ---------------- single-kernel ticketed scan ----------------
// block-local exclusive scan + atomic base ticket (bucket ranges disjoint;
// absolute placement run-varying, contents identical)
__global__ void __launch_bounds__(256) k_scanA(void) {
    __shared__ int sh[256];
    __shared__ int sbase;
    int i = blockIdx.x * 256 + threadIdx.x;
    int tid = threadIdx.x;
    int v = (i < NN) ? g_cnt[i] : 0;
    sh[tid] = v;
    __syncthreads();
#pragma unroll
    for (int off = 1; off < 256; off <<= 1) {
        int u = 0;
        if (tid >= off) u = sh[tid - off];
        __syncthreads();
        if (tid >= off) sh[tid] += u;
        __syncthreads();
    }
    if (tid == 255) sbase = atomicAdd(&g_total, sh[255]);
    __syncthreads();
    if (i < NN) {
        int start = sbase + sh[tid] - v;
        g_off[i]  = start;
        g_kcur[i] = start;
    }
}

// ---------------- permute: payload sorted by dst ----------------
__global__ void k_permute(void) {
    int e = blockIdx.x * 256 + threadIdx.x;
    if (e >= EE) return;
    int d = __ldg(&g_edst[e]);
    int pos = atomicAdd(&g_kcur[d], 1);
    g_sedge[pos] = __ldg(&g_pack[e]);
}

// ---------------- segmented sum: out[d] = relu(sum_e y[pack_e] + b) --------
// half-warp (16 lanes = 16 float4 cols) per dst; 4-way unrolled gathers.
__global__ void __launch_bounds__(256) k_segsum(const float* __restrict__ y,
                                                const float* __restrict__ bias,
                                                float* __restrict__ out) {
    int tid = threadIdx.x;
    int warpid = tid >> 5, lane = tid & 31;
    int eh = lane >> 4;
    int li = lane & 15;
    int d = blockIdx.x * 16 + warpid * 2 + eh;
    if (d >= NN) return;

    int start = __ldg(&g_off[d]);
    int cnt   = __ldg(&g_cnt[d]);
    const int* se = g_sedge + start;
    const float4* yv = (const float4*)y;

    float4 a0 = make_float4(0.f, 0.f, 0.f, 0.f);
    float4 a1 = a0, a2 = a0, a3 = a0;

    int e = 0;
    for (; e + 4 <= cnt; e += 4) {
        int i0 = __ldg(se + e);
        int i1 = __ldg(se + e + 1);
        int i2 = __ldg(se + e + 2);
        int i3 = __ldg(se + e + 3);
        float4 v0 = __ldg(&yv[(size_t)i0 * 16 + li]);
        float4 v1 = __ldg(&yv[(size_t)i1 * 16 + li]);
        float4 v2 = __ldg(&yv[(size_t)i2 * 16 + li]);
        float4 v3 = __ldg(&yv[(size_t)i3 * 16 + li]);
        a0.x += v0.x; a0.y += v0.y; a0.z += v0.z; a0.w += v0.w;
        a1.x += v1.x; a1.y += v1.y; a1.z += v1.z; a1.w += v1.w;
        a2.x += v2.x; a2.y += v2.y; a2.z += v2.z; a2.w += v2.w;
        a3.x += v3.x; a3.y += v3.y; a3.z += v3.z; a3.w += v3.w;
    }
    for (; e < cnt; e++) {
        int i0 = __ldg(se + e);
        float4 v0 = __ldg(&yv[(size_t)i0 * 16 + li]);
        a0.x += v0.x; a0.y += v0.y; a0.z += v0.z; a0.w += v0.w;
    }

    a0.x += a1.x + a2.x + a3.x;
    a0.y += a1.y + a2.y + a3.y;
    a0.z += a1.z + a2.z + a3.z;
    a0.w += a1.w + a2.w + a3.w;

    float4 bv = __ldg(&((const float4*)bias)[li]);
    float4 r;
    r.x = fmaxf(a0.x + bv.x, 0.f);
    r.y = fmaxf(a0.y + bv.y, 0.f);
    r.z = fmaxf(a0.z + bv.z, 0.f);
    r.w = fmaxf(a0.w + bv.w, 0.f);
    ((float4*)out)[(size_t)d * 16 + li] = r;
}

// ---------------- ssl = h2 @ Wssl + bssl ----------------
__global__ void __launch_bounds__(256) k_ssl(const float* __restrict__ h2,
                                             const float* __restrict__ Wssl,
                                             const float* __restrict__ bssl,
                                             float* __restrict__ out) {
    __shared__ float ws[64 * 64];
    __shared__ float hs[4 * 64];
    int tid = threadIdx.x;
    int nb  = blockIdx.x * 4;

    {
        float4* wsv = (float4*)ws;
        const float4* Wv = (const float4*)Wssl;
#pragma unroll
        for (int k = 0; k < 4; k++) wsv[tid + k * 256] = Wv[tid + k * 256];
        hs[tid] = h2[(size_t)nb * 64 + tid];
    }
    __syncthreads();

    int nl = tid >> 6;
    int fo = tid & 63;
    float a = __ldg(&bssl[fo]);
#pragma unroll 8
    for (int fin = 0; fin < 64; ++fin)
        a += hs[nl * 64 + fin] * ws[fin * 64 + fo];
    out[(size_t)(nb + nl) * 64 + fo] = a;
}

// ---------------- launch ----------------
extern "C" void kernel_launch(void* const* d_in, const int* in_sizes, int n_in,
                              void* d_out, int out_size) {
    const float* x    = (const float*)d_in[0];
    const void*  ei   = d_in[1];
    const void*  ti   = d_in[2];
    const float* W1   = (const float*)d_in[3];
    const float* b1   = (const float*)d_in[4];
    const float* W2   = (const float*)d_in[5];
    const float* b2   = (const float*)d_in[6];
    const float* Wssl = (const float*)d_in[7];
    const float* bssl = (const float*)d_in[8];
    float* out_h   = (float*)d_out;
    float* out_ssl = (float*)d_out + (size_t)NN * 64;

    float* dV1;  cudaGetSymbolAddress((void**)&dV1, g_V1);
    float* dV2;  cudaGetSymbolAddress((void**)&dV2, g_V2);
    float* dy;   cudaGetSymbolAddress((void**)&dy, g_y);
    float* dh1;  cudaGetSymbolAddress((void**)&dh1, g_h1);

    // 1: init (mode detect + zero + W permutes)
    k_init<<<INIT_BLKS, 256>>>((const int*)ei, W1, W2);
    // 2: gemm layer 1 (independent of sort)
    k_gemm<<<NN / 16, 128>>>(x, dV1, dy);
    // 3-5: counting sort by dst
    k_hist<<<EE / 256, 256>>>(ei, ti);
    k_scanA<<<INIT_BLKS, 256>>>();
    k_permute<<<EE / 256, 256>>>();
    // 6: segmented sum layer 1  (<- ncu -s 5 -c 1 profiles this)
    k_segsum<<<(NN + 15) / 16, 256>>>(dy, b1, dh1);
    // 7-8: layer 2
    k_gemm<<<NN / 16, 128>>>(dh1, dV2, dy);
    k_segsum<<<(NN + 15) / 16, 256>>>(dy, b2, out_h);
    // 9: ssl head
    k_ssl<<<NN / 4, 256>>>(out_h, Wssl, bssl, out_ssl);
}